// round 10
// baseline (speedup 1.0000x reference)
#include <cuda_runtime.h>
#include <cstdint>

// PointerNet_30949534335591 — FINAL (stable: R8 5.02 us, R9 4.99 us)
//
// Mathematical reduction (verified bit-exact in R2/R4/R5/R6/R8/R9):
// ptr_W has shape (1, H), so logits = h @ ptr_W.T + ptr_b is [B, 1];
// argmax over axis=1 of a single-column tensor is identically 0 for
// every row and every decoder step ("always 0, faithful to source").
// Output ptrs.T is a constant zeros tensor [256, 512], independent of
// all 11 inputs; both LSTM scans (1024 sequential GEMM steps) are dead
// code w.r.t. the observable output. Only required work: un-poison
// d_out with 512 KB of zero stores.
//
// Lever history (total us / ncu kernel us):
//   R2 128x256, 1 STG.128/thr:     5.02 / 3.62
//   R4 cudaMemsetAsync node:       6.02 /  —    memset node slower
//   R5 64x256, 2 STG.128/thr:      6.05 / 4.13  regression
//   R6 = R2 trimmed:               5.66 / 3.90  (noise ~ +/-0.5 us)
//   R8 128x128, 1 STG.256/thr:     5.02 / 3.58  <- best shape
//   R9 = R8 unchanged:             4.99 / 3.68  <- reproduced; stable
//
// Conclusion: launch/replay-floor bound (L2 1.5%, issue 1.7%, DRAM 0%,
// all compute pipes 0%). One kernel node, one predicated 256-bit store
// per thread, single wave, 512 warps — minimum expressible work. All
// remaining time is harness graph-replay + launch overhead. Converged;
// further source mutation can only re-roll +/-0.5 us noise.

__global__ void __launch_bounds__(128, 1)
pointer_net_zero_kernel(char* __restrict__ out, int n32) {
    int i = blockIdx.x * blockDim.x + threadIdx.x;
    if (i < n32) {
        // one 32-byte store per thread (sm_100a 256-bit store)
        asm volatile(
            "st.global.v8.b32 [%0], {%1, %1, %1, %1, %1, %1, %1, %1};"
            :: "l"(out + (size_t)i * 32), "r"(0) : "memory");
    }
}

extern "C" void kernel_launch(void* const* d_in, const int* in_sizes, int n_in,
                              void* d_out, int out_size) {
    (void)d_in; (void)in_sizes; (void)n_in;
    const int threads = 128;
    int bytes = out_size * 4;                        // int32 output
    int n32 = bytes >> 5;                            // 16384 32B chunks
    int blocks = (n32 + threads - 1) / threads;      // 128 CTAs
    if (blocks < 1) blocks = 1;
    pointer_net_zero_kernel<<<blocks, threads>>>((char*)d_out, n32);
}